// round 8
// baseline (speedup 1.0000x reference)
#include <cuda_runtime.h>
#include <math.h>

// Chamfer loss, B=4, C=3, Np=Ng=8192. R8:
//  R7 structure (TGQ=128, single barrier/stage, double-buffered, prefetch)
//  + f32x2 packing along the p dimension: two p-rows per packed op.
//    p packs = (a0,a1) adjacent scalars (no duplication);
//    g broadcast pairs (g,g) come from duplicated smem via LDS.64.
//  Per 2 pairs: 3 FFMA2 + 1 FADD2 + 4 FMNMX = 4 issue slots/pair (was 6).
//  Evidence: R6/R7 profiles show issue-slot-bound (issue 59->68%, fma 33-36%).
// sqrt only on final mins (monotone). Col-min via int atomicMin on positive
// clamped float bits (order-independent => deterministic).

#define BATCH   4
#define NPT     8192
#define TPQ     128                      // predict points per block
#define TGQ     128                      // gt points per stage
#define NSTAGES (NPT / TGQ)              // 64
#define NTH     256                      // 16 (g=tx) x 16 (p=ty)
#define EPSF    1e-12f
#define FLTMAXI 0x7f7fffff

typedef unsigned long long u64;

__device__ int   g_colmin[BATCH * NPT];
__device__ float g_rowsum[BATCH * (NPT / TPQ)];

#define INIT_CHUNK ((BATCH * NPT) / 3 + 1)
__global__ void init_kernel(int base) {
    int i = base + blockIdx.x * blockDim.x + threadIdx.x;
    if (i < BATCH * NPT) g_colmin[i] = FLTMAXI;
}

__device__ __forceinline__ u64 pk2(float lo, float hi) {
    u64 r; asm("mov.b64 %0,{%1,%2};" : "=l"(r) : "f"(lo), "f"(hi)); return r;
}
__device__ __forceinline__ void upk2(float& lo, float& hi, u64 v) {
    asm("mov.b64 {%0,%1},%2;" : "=f"(lo), "=f"(hi) : "l"(v));
}
__device__ __forceinline__ u64 ffma2(u64 a, u64 b, u64 c) {
    u64 d; asm("fma.rn.f32x2 %0,%1,%2,%3;" : "=l"(d) : "l"(a), "l"(b), "l"(c)); return d;
}
__device__ __forceinline__ u64 fadd2(u64 a, u64 b) {
    u64 d; asm("add.rn.f32x2 %0,%1,%2;" : "=l"(d) : "l"(a), "l"(b)); return d;
}

__global__ __launch_bounds__(NTH, 3)
void chamfer_main(const float* __restrict__ P, const float* __restrict__ G) {
    const int b     = blockIdx.y;
    const int pbase = blockIdx.x * TPQ;
    const float* Pb = P + (size_t)b * 3 * NPT;
    const float* Gb = G + (size_t)b * 3 * NPT;
    const int tid = threadIdx.x;
    const int tx  = tid & 15;        // g direction
    const int ty  = tid >> 4;        // p direction

    __shared__ float4 sp[TPQ];
    // duplicated g attributes: element i holds (v_i, v_i) -> LDS.64 gives a
    // ready broadcast pack for f32x2 ops. Bank = 2*tx (conflict-free), ty broadcasts.
    __shared__ float2 sgx[2][TGQ], sgy[2][TGQ], sgz[2][TGQ], sg2[2][TGQ];
    __shared__ float  cbuf[2][16][TGQ + 1];     // double buffer, padded

    // ---- prologue: prefetch stage-0 gt, load & transform p tile ----
    float rx = 0.f, ry = 0.f, rz = 0.f;
    if (tid < TGQ) {
        rx = Gb[tid];
        ry = Gb[NPT + tid];
        rz = Gb[2 * NPT + tid];
    }
    for (int i = tid; i < TPQ; i += NTH) {
        float px = Pb[pbase + i];
        float py = Pb[NPT + pbase + i];
        float pz = Pb[2 * NPT + pbase + i];
        sp[i] = make_float4(-2.f * px, -2.f * py, -2.f * pz,
                            px * px + py * py + pz * pz);
    }
    if (tid < TGQ) {
        sgx[0][tid] = make_float2(rx, rx);
        sgy[0][tid] = make_float2(ry, ry);
        sgz[0][tid] = make_float2(rz, rz);
        float r2 = rx * rx + ry * ry + rz * rz;
        sg2[0][tid] = make_float2(r2, r2);
    }
    __syncthreads();

    // p packs: pair rows (2*ii2, 2*ii2+1); no duplication.
    u64 pa2[4], pb2[4], pc2[4], pp2k[4];
    float rowmin[8];
#pragma unroll
    for (int ii2 = 0; ii2 < 4; ii2++) {
        float4 v0 = sp[ty * 8 + 2 * ii2];
        float4 v1 = sp[ty * 8 + 2 * ii2 + 1];
        pa2[ii2]  = pk2(v0.x, v1.x);
        pb2[ii2]  = pk2(v0.y, v1.y);
        pc2[ii2]  = pk2(v0.z, v1.z);
        pp2k[ii2] = pk2(v0.w, v1.w);
        rowmin[2 * ii2] = 3.4e38f; rowmin[2 * ii2 + 1] = 3.4e38f;
    }

    for (int s = 0; s < NSTAGES; s++) {
        const int cur = s & 1, nxt = cur ^ 1;

        // issue next-stage gmem loads now; latency hidden under compute
        if (s + 1 < NSTAGES && tid < TGQ) {
            int g = (s + 1) * TGQ + tid;
            rx = Gb[g]; ry = Gb[NPT + g]; rz = Gb[2 * NPT + g];
        }

        // two g-passes of 64 columns each (RG=4)
#pragma unroll
        for (int h = 0; h < 2; h++) {
            float colmin[4];
#pragma unroll
            for (int jj = 0; jj < 4; jj++) colmin[jj] = 3.4e38f;

#pragma unroll
            for (int jj = 0; jj < 4; jj++) {
                const int gi = h * 64 + jj * 16 + tx;
                u64 gxb = *reinterpret_cast<const u64*>(&sgx[cur][gi]);
                u64 gyb = *reinterpret_cast<const u64*>(&sgy[cur][gi]);
                u64 gzb = *reinterpret_cast<const u64*>(&sgz[cur][gi]);
                u64 g2b = *reinterpret_cast<const u64*>(&sg2[cur][gi]);
#pragma unroll
                for (int ii2 = 0; ii2 < 4; ii2++) {
                    u64 e = ffma2(pc2[ii2], gzb, g2b);
                    e = ffma2(pb2[ii2], gyb, e);
                    e = ffma2(pa2[ii2], gxb, e);
                    u64 d2 = fadd2(e, pp2k[ii2]);     // (d2_row0, d2_row1)
                    float d0, d1; upk2(d0, d1, d2);
                    rowmin[2 * ii2]     = fminf(rowmin[2 * ii2],     d0);
                    rowmin[2 * ii2 + 1] = fminf(rowmin[2 * ii2 + 1], d1);
                    colmin[jj] = fminf(colmin[jj], fminf(d0, d1));
                }
            }

            // per-warp column partials (pre-barrier stores)
#pragma unroll
            for (int jj = 0; jj < 4; jj++)
                cbuf[cur][ty][h * 64 + jj * 16 + tx] = colmin[jj];
        }

        // stage s+1 gt chunk -> other smem buffer (prefetch regs landed)
        if (s + 1 < NSTAGES && tid < TGQ) {
            sgx[nxt][tid] = make_float2(rx, rx);
            sgy[nxt][tid] = make_float2(ry, ry);
            sgz[nxt][tid] = make_float2(rz, rz);
            float r2 = rx * rx + ry * ry + rz * rz;
            sg2[nxt][tid] = make_float2(r2, r2);
        }

        __syncthreads();   // the ONLY barrier per stage

        // column reduce overlaps next stage's compute in the other warps
        if (tid < TGQ) {
            float v[16];
#pragma unroll
            for (int t = 0; t < 16; t++) v[t] = cbuf[cur][t][tid];
#pragma unroll
            for (int st = 8; st > 0; st >>= 1)
#pragma unroll
                for (int t = 0; t < 8; t++)
                    if (t < st) v[t] = fminf(v[t], v[t + st]);
            float m = fmaxf(v[0], EPSF);   // clamp (ref); positive => int order valid
            atomicMin(&g_colmin[b * NPT + s * TGQ + tid], __float_as_int(m));
        }
    }

    // row-min reduce across tx: lanes differing in low 4 bits share ty and
    // partition g columns -> xor-shuffle over 1,2,4,8 completes the min.
    // rowmin already holds d2 (p2 folded in by the packed FADD2).
#pragma unroll
    for (int ii = 0; ii < 8; ii++) {
        float m = rowmin[ii];
#pragma unroll
        for (int off = 1; off < 16; off <<= 1)
            m = fminf(m, __shfl_xor_sync(0xffffffffu, m, off));
        rowmin[ii] = m;
    }

    float rsum = 0.f;
    if (tx == 0) {
#pragma unroll
        for (int ii = 0; ii < 8; ii++)
            rsum += sqrtf(fmaxf(rowmin[ii], EPSF));
    }

    __shared__ float sred[NTH];
    sred[tid] = rsum;
    __syncthreads();
    for (int st = NTH / 2; st > 0; st >>= 1) {
        if (tid < st) sred[tid] += sred[tid + st];
        __syncthreads();
    }
    if (tid == 0)
        g_rowsum[b * gridDim.x + blockIdx.x] = sred[0];
}

__global__ void finalize_kernel(float* out, int nblocks) {
    __shared__ float sred[256];
    const int tid = threadIdx.x;
    float s = 0.f;
    for (int i = tid; i < BATCH * NPT; i += 256)
        s += sqrtf(__int_as_float(g_colmin[i]));   // already clamped >= EPS
    for (int i = tid; i < nblocks; i += 256)
        s += g_rowsum[i];
    sred[tid] = s;
    __syncthreads();
    for (int st = 128; st > 0; st >>= 1) {
        if (tid < st) sred[tid] += sred[tid + st];
        __syncthreads();
    }
    if (tid == 0)
        out[0] = sred[0] / (float)(BATCH * 2 * NPT);   // denom = B*(Np+Ng)
}

extern "C" void kernel_launch(void* const* d_in, const int* in_sizes, int n_in,
                              void* d_out, int out_size) {
    const float* P = (const float*)d_in[0];
    const float* G = (const float*)d_in[1];

    // three init launches so chamfer_main is kernel-launch index 3 (ncu target)
    init_kernel<<<(INIT_CHUNK + 255) / 256, 256>>>(0);
    init_kernel<<<(INIT_CHUNK + 255) / 256, 256>>>(INIT_CHUNK);
    init_kernel<<<(INIT_CHUNK + 255) / 256, 256>>>(2 * INIT_CHUNK);

    dim3 grid(NPT / TPQ, BATCH);             // 64 x 4 = 256 blocks
    chamfer_main<<<grid, NTH>>>(P, G);

    finalize_kernel<<<1, 256>>>((float*)d_out, BATCH * (NPT / TPQ));
}